// round 11
// baseline (speedup 1.0000x reference)
#include <cuda_runtime.h>
#include <cuda_fp16.h>
#include <math.h>
#include <stdint.h>

// Problem constants (fixed by reference)
#define NN   8192
#define EMB  125
#define POSD 3
#define FIN  128     // EMB + POSD
#define HID  512
#define SLOTS 256

#define W0_ELEMS (FIN * HID)          // 65536
#define W_ELEMS  (HID * HID)          // 262144
#define WH_TOTAL (W0_ELEMS + 3 * W_ELEMS)  // 851968

// ---------------- device scratch (no allocation allowed) ----------------
__device__ int   g_col[NN * SLOTS];
__device__ int   g_deg[NN];
__device__ float g_norm[NN];
__device__ __align__(16) __half g_hbufA[NN * HID];   // 8 MB
__device__ __align__(16) __half g_hbufB[NN * HID];   // 8 MB
__device__ __align__(16) __half g_wh[WH_TOTAL];      // 1.7 MB fp16 weights

// ---------------- 1) build sparse structure + norms ----------------
__global__ void build_kernel(const float* __restrict__ adj) {
    int warp = threadIdx.x >> 5;
    int lane = threadIdx.x & 31;
    int row  = blockIdx.x * (blockDim.x >> 5) + warp;
    if (row >= NN) return;

    const float* arow = adj + (size_t)row * NN;
    int cnt = 0;
    for (int c0 = 0; c0 < NN; c0 += 32) {
        int c = c0 + lane;
        float v = arow[c];
        bool pred = (v != 0.0f) && (c != row);
        unsigned mask = __ballot_sync(0xFFFFFFFFu, pred);
        int pos = cnt + __popc(mask & ((1u << lane) - 1u));
        if (pred && pos < SLOTS) g_col[row * SLOTS + pos] = c;
        cnt += __popc(mask);
    }
    if (lane == 0) {
        g_deg[row]  = (cnt < SLOTS) ? cnt : SLOTS;
        g_norm[row] = rsqrtf(fmaxf((float)cnt, 1.0f));
    }
}

// ---------------- 2) concat emb||pos -> fp16 feat [NN, FIN] ----------------
__global__ void concat_kernel(const float* __restrict__ emb,
                              const float* __restrict__ pos,
                              __half* __restrict__ out) {
    int idx = blockIdx.x * blockDim.x + threadIdx.x;
    if (idx >= NN * FIN) return;
    int i = idx / FIN, c = idx % FIN;
    float v = (c < EMB) ? emb[i * EMB + c] : pos[i * POSD + (c - EMB)];
    out[idx] = __float2half(v);
}

// ---------------- 2b) convert weights to fp16 (compact layout) ----------------
__global__ void wconv_kernel(const float* __restrict__ W0, const float* __restrict__ W1,
                             const float* __restrict__ W2, const float* __restrict__ W3) {
    int idx = (blockIdx.x * blockDim.x + threadIdx.x) * 8;
    if (idx >= WH_TOTAL) return;
    const float* src;
    if (idx < W0_ELEMS)                    src = W0 + idx;
    else if (idx < W0_ELEMS + W_ELEMS)     src = W1 + (idx - W0_ELEMS);
    else if (idx < W0_ELEMS + 2 * W_ELEMS) src = W2 + (idx - W0_ELEMS - W_ELEMS);
    else                                   src = W3 + (idx - W0_ELEMS - 2 * W_ELEMS);
    float4 a = *(const float4*)src;
    float4 b = *(const float4*)(src + 4);
    __half2 h[4];
    h[0] = __floats2half2_rn(a.x, a.y);
    h[1] = __floats2half2_rn(a.z, a.w);
    h[2] = __floats2half2_rn(b.x, b.y);
    h[3] = __floats2half2_rn(b.z, b.w);
    *(uint4*)&g_wh[idx] = *(uint4*)h;
}

// ---------------- 3) SpMM fp16: agg[i,:] = norm_i * sum_j norm_j * feat[j,:] ----------------
// blockDim = (C/8, 128/(C/8)); each thread handles 8 halves (one uint4).
template <int C>
__global__ void spmm_fp16(const __half* __restrict__ feat, __half* __restrict__ agg) {
    constexpr int TX = C / 8;
    constexpr int TY = 128 / TX;
    int y = threadIdx.y;
    int i = blockIdx.x * TY + y;
    __shared__ int   sc[TY][SLOTS];
    __shared__ float sw[TY][SLOTS];
    int d = g_deg[i];
    for (int k = threadIdx.x; k < d; k += TX) {
        int j = g_col[i * SLOTS + k];
        sc[y][k] = j;
        sw[y][k] = g_norm[j];
    }
    __syncthreads();
    int c8 = threadIdx.x * 8;
    float acc[8] = {0.f, 0.f, 0.f, 0.f, 0.f, 0.f, 0.f, 0.f};
    for (int k = 0; k < d; k++) {
        float w = sw[y][k];
        uint4 v = *(const uint4*)&feat[(size_t)sc[y][k] * C + c8];
        const __half2* hv = (const __half2*)&v;
#pragma unroll
        for (int q = 0; q < 4; q++) {
            float2 f = __half22float2(hv[q]);
            acc[q * 2 + 0] = fmaf(w, f.x, acc[q * 2 + 0]);
            acc[q * 2 + 1] = fmaf(w, f.y, acc[q * 2 + 1]);
        }
    }
    float ni = g_norm[i];
    __half2 ho[4];
#pragma unroll
    for (int q = 0; q < 4; q++)
        ho[q] = __floats2half2_rn(acc[q * 2] * ni, acc[q * 2 + 1] * ni);
    *(uint4*)&agg[(size_t)i * C + c8] = *(uint4*)ho;
}

// ---------------- 4) fp16 tensor GEMM + bias + softplus ----------------
__device__ __forceinline__ void mma_f16(float* d, const uint32_t* a, const uint32_t* b) {
    asm volatile(
        "mma.sync.aligned.m16n8k16.row.col.f32.f16.f16.f32 "
        "{%0,%1,%2,%3}, {%4,%5,%6,%7}, {%8,%9}, {%0,%1,%2,%3};\n"
        : "+f"(d[0]), "+f"(d[1]), "+f"(d[2]), "+f"(d[3])
        : "r"(a[0]), "r"(a[1]), "r"(a[2]), "r"(a[3]), "r"(b[0]), "r"(b[1]));
}

__device__ __forceinline__ void ldmat_x4(uint32_t* r, uint32_t saddr) {
    asm volatile(
        "ldmatrix.sync.aligned.m8n8.x4.shared.b16 {%0,%1,%2,%3}, [%4];\n"
        : "=r"(r[0]), "=r"(r[1]), "=r"(r[2]), "=r"(r[3])
        : "r"(saddr));
}

__device__ __forceinline__ void ldmat_x4_trans(uint32_t* r, uint32_t saddr) {
    asm volatile(
        "ldmatrix.sync.aligned.m8n8.x4.trans.shared.b16 {%0,%1,%2,%3}, [%4];\n"
        : "=r"(r[0]), "=r"(r[1]), "=r"(r[2]), "=r"(r[3])
        : "r"(saddr));
}

// Block tile 128x128, BK=32 (fp16), 8 warps (2x4), warp tile 64x32.
// A smem [m][k] LDA=40 halves; B smem [k][n] LDB=136 halves. All ldmatrix paths
// and STS.128 store phases verified bank-conflict-free.
template <int K, bool OUT_HALF>
__global__ __launch_bounds__(256, 2) void gemm_f16_softplus(
    const __half* __restrict__ A,
    const __half* __restrict__ Bh,
    const float* __restrict__ bias,
    void* __restrict__ CoutV)
{
    constexpr int BM = 128, BN = 128, BK = 32;
    constexpr int LDA = BK + 8;   // 40 halves (80B; rows 0..7 -> distinct bank quads)
    constexpr int LDB = BN + 8;   // 136 halves (272B; k-rows stride 4 banks)

    __shared__ __align__(16) __half As[2][BM][LDA];  // 20 KB
    __shared__ __align__(16) __half Bs[2][BK][LDB];  // 17 KB

    int tid  = threadIdx.x;
    int lane = tid & 31;
    int warp = tid >> 5;
    int g    = lane >> 2;
    int tg   = lane & 3;
    int wm   = (warp & 1) * 64;
    int wn   = (warp >> 1) * 32;
    int m0   = blockIdx.y * BM;
    int n0   = blockIdx.x * BN;

    int lmrow = lane & 15;
    int lmhi  = (lane >> 4) * 8;

    float acc[4][4][4];
#pragma unroll
    for (int i = 0; i < 4; i++)
#pragma unroll
        for (int j = 0; j < 4; j++)
#pragma unroll
            for (int r = 0; r < 4; r++) acc[i][j][r] = 0.0f;

    // global staging regs
    uint4 pa[2], pb[2];
    // A mapping: i in {0,1}: row = tid&127, col8 = ((tid>>7)*2 + i)*8
    int a_row = tid & 127;
    int a_c0  = ((tid >> 7) * 2) * 8;
    // B mapping: f = i*256 + tid: row = f>>4, col8 = (f&15)*8

    auto loadg = [&](int k0) {
#pragma unroll
        for (int i = 0; i < 2; i++) {
            pa[i] = *(const uint4*)&A[(size_t)(m0 + a_row) * K + k0 + a_c0 + i * 8];
            int f  = i * 256 + tid;
            int rb = f >> 4, cb = (f & 15) * 8;
            pb[i] = *(const uint4*)&Bh[(size_t)(k0 + rb) * HID + n0 + cb];
        }
    };
    auto stores = [&](int buf) {
#pragma unroll
        for (int i = 0; i < 2; i++) {
            *(uint4*)&As[buf][a_row][a_c0 + i * 8] = pa[i];
            int f  = i * 256 + tid;
            int rb = f >> 4, cb = (f & 15) * 8;
            *(uint4*)&Bs[buf][rb][cb] = pb[i];
        }
    };
    auto compute = [&](int buf) {
#pragma unroll
        for (int ks = 0; ks < BK; ks += 16) {
            uint32_t a[4][4], b[4][2];
#pragma unroll
            for (int i = 0; i < 4; i++) {
                uint32_t saddr = (uint32_t)__cvta_generic_to_shared(
                    &As[buf][wm + i * 16 + lmrow][ks + lmhi]);
                ldmat_x4(a[i], saddr);
            }
#pragma unroll
            for (int jj = 0; jj < 2; jj++) {
                uint32_t r[4];
                uint32_t saddr = (uint32_t)__cvta_generic_to_shared(
                    &Bs[buf][ks + lmrow][wn + jj * 16 + lmhi]);
                ldmat_x4_trans(r, saddr);
                b[jj * 2 + 0][0] = r[0]; b[jj * 2 + 0][1] = r[1];
                b[jj * 2 + 1][0] = r[2]; b[jj * 2 + 1][1] = r[3];
            }
#pragma unroll
            for (int i = 0; i < 4; i++)
#pragma unroll
                for (int j = 0; j < 4; j++)
                    mma_f16(acc[i][j], a[i], b[j]);
        }
    };

    constexpr int NK = K / BK;
    loadg(0);
    stores(0);
    __syncthreads();
#pragma unroll 1
    for (int t = 0; t < NK; t++) {
        if (t + 1 < NK) loadg((t + 1) * BK);
        compute(t & 1);
        if (t + 1 < NK) {
            stores((t + 1) & 1);
            __syncthreads();
        }
    }

    // epilogue: bias + fast stable softplus
#pragma unroll
    for (int i = 0; i < 4; i++) {
        int row = m0 + wm + i * 16 + g;
#pragma unroll
        for (int j = 0; j < 4; j++) {
            int col = n0 + wn + j * 8 + tg * 2;
            float bx = bias[col], by = bias[col + 1];
            float x0 = acc[i][j][0] + bx;
            float x1 = acc[i][j][1] + by;
            float x2 = acc[i][j][2] + bx;
            float x3 = acc[i][j][3] + by;
            float s0 = fmaxf(x0, 0.f) + __logf(1.0f + __expf(-fabsf(x0)));
            float s1 = fmaxf(x1, 0.f) + __logf(1.0f + __expf(-fabsf(x1)));
            float s2 = fmaxf(x2, 0.f) + __logf(1.0f + __expf(-fabsf(x2)));
            float s3 = fmaxf(x3, 0.f) + __logf(1.0f + __expf(-fabsf(x3)));
            if (OUT_HALF) {
                __half* C = (__half*)CoutV;
                *(__half2*)&C[(size_t)row * HID + col]       = __floats2half2_rn(s0, s1);
                *(__half2*)&C[(size_t)(row + 8) * HID + col] = __floats2half2_rn(s2, s3);
            } else {
                float* C = (float*)CoutV;
                *(float2*)&C[(size_t)row * HID + col]       = make_float2(s0, s1);
                *(float2*)&C[(size_t)(row + 8) * HID + col] = make_float2(s2, s3);
            }
        }
    }
}

// ---------------- launch ----------------
extern "C" void kernel_launch(void* const* d_in, const int* in_sizes, int n_in,
                              void* d_out, int out_size) {
    const float* atom_pos = (const float*)d_in[0];
    const float* dist_adj = (const float*)d_in[1];
    const float* atom_emb = (const float*)d_in[2];
    const float* W0 = (const float*)d_in[3];
    const float* b0 = (const float*)d_in[4];
    const float* W1 = (const float*)d_in[5];
    const float* b1 = (const float*)d_in[6];
    const float* W2 = (const float*)d_in[7];
    const float* b2 = (const float*)d_in[8];
    const float* W3 = (const float*)d_in[9];
    const float* b3 = (const float*)d_in[10];
    float* out = (float*)d_out;

    __half *bufA, *bufB, *wh;
    cudaGetSymbolAddress((void**)&bufA, g_hbufA);
    cudaGetSymbolAddress((void**)&bufB, g_hbufB);
    cudaGetSymbolAddress((void**)&wh,   g_wh);

    const __half* WH0 = wh;
    const __half* WH1 = wh + W0_ELEMS;
    const __half* WH2 = wh + W0_ELEMS + W_ELEMS;
    const __half* WH3 = wh + W0_ELEMS + 2 * W_ELEMS;

    build_kernel<<<NN / 8, 256>>>(dist_adj);
    concat_kernel<<<(NN * FIN + 255) / 256, 256>>>(atom_emb, atom_pos, bufA);
    wconv_kernel<<<(WH_TOTAL / 8 + 255) / 256, 256>>>(W0, W1, W2, W3);

    dim3 ggrid(HID / 128, NN / 128);   // (4, 64)

    // Layer 0: K = FIN = 128
    spmm_fp16<FIN><<<NN / 8, dim3(16, 8)>>>(bufA, bufB);
    gemm_f16_softplus<FIN, true><<<ggrid, 256>>>(bufB, WH0, b0, bufA);

    // Layer 1
    spmm_fp16<HID><<<NN / 2, dim3(64, 2)>>>(bufA, bufB);
    gemm_f16_softplus<HID, true><<<ggrid, 256>>>(bufB, WH1, b1, bufA);

    // Layer 2
    spmm_fp16<HID><<<NN / 2, dim3(64, 2)>>>(bufA, bufB);
    gemm_f16_softplus<HID, true><<<ggrid, 256>>>(bufB, WH2, b2, bufA);

    // Layer 3 -> fp32 to d_out
    spmm_fp16<HID><<<NN / 2, dim3(64, 2)>>>(bufA, bufB);
    gemm_f16_softplus<HID, false><<<ggrid, 256>>>(bufB, WH3, b3, out);
}

// round 12
// speedup vs baseline: 1.0006x; 1.0006x over previous
#include <cuda_runtime.h>
#include <cuda_fp16.h>
#include <math.h>
#include <stdint.h>

// Problem constants (fixed by reference)
#define NN   8192
#define EMB  125
#define POSD 3
#define FIN  128     // EMB + POSD
#define HID  512
#define SLOTS 256

#define W0_ELEMS (FIN * HID)          // 65536
#define W_ELEMS  (HID * HID)          // 262144
#define WH_TOTAL (W0_ELEMS + 3 * W_ELEMS)  // 851968

// ---------------- device scratch (no allocation allowed) ----------------
__device__ int   g_col[NN * SLOTS];
__device__ int   g_deg[NN];
__device__ float g_norm[NN];
__device__ __align__(16) __half g_hbufA[NN * HID];   // 8 MB
__device__ __align__(16) __half g_hbufB[NN * HID];   // 8 MB
__device__ __align__(16) __half g_wh[WH_TOTAL];      // 1.7 MB fp16 weights

// ---------------- 1) build sparse structure + norms ----------------
__global__ void build_kernel(const float* __restrict__ adj) {
    int warp = threadIdx.x >> 5;
    int lane = threadIdx.x & 31;
    int row  = blockIdx.x * (blockDim.x >> 5) + warp;
    if (row >= NN) return;

    const float* arow = adj + (size_t)row * NN;
    int cnt = 0;
    for (int c0 = 0; c0 < NN; c0 += 32) {
        int c = c0 + lane;
        float v = arow[c];
        bool pred = (v != 0.0f) && (c != row);
        unsigned mask = __ballot_sync(0xFFFFFFFFu, pred);
        int pos = cnt + __popc(mask & ((1u << lane) - 1u));
        if (pred && pos < SLOTS) g_col[row * SLOTS + pos] = c;
        cnt += __popc(mask);
    }
    if (lane == 0) {
        g_deg[row]  = (cnt < SLOTS) ? cnt : SLOTS;
        g_norm[row] = rsqrtf(fmaxf((float)cnt, 1.0f));
    }
}

// ---------------- 2) concat emb||pos -> fp16 feat [NN, FIN] ----------------
__global__ void concat_kernel(const float* __restrict__ emb,
                              const float* __restrict__ pos,
                              __half* __restrict__ out) {
    int idx = blockIdx.x * blockDim.x + threadIdx.x;
    if (idx >= NN * FIN) return;
    int i = idx / FIN, c = idx % FIN;
    float v = (c < EMB) ? emb[i * EMB + c] : pos[i * POSD + (c - EMB)];
    out[idx] = __float2half(v);
}

// ---------------- 2b) convert weights to fp16 (compact layout) ----------------
__global__ void wconv_kernel(const float* __restrict__ W0, const float* __restrict__ W1,
                             const float* __restrict__ W2, const float* __restrict__ W3) {
    int idx = (blockIdx.x * blockDim.x + threadIdx.x) * 8;
    if (idx >= WH_TOTAL) return;
    const float* src;
    if (idx < W0_ELEMS)                    src = W0 + idx;
    else if (idx < W0_ELEMS + W_ELEMS)     src = W1 + (idx - W0_ELEMS);
    else if (idx < W0_ELEMS + 2 * W_ELEMS) src = W2 + (idx - W0_ELEMS - W_ELEMS);
    else                                   src = W3 + (idx - W0_ELEMS - 2 * W_ELEMS);
    float4 a = *(const float4*)src;
    float4 b = *(const float4*)(src + 4);
    __half2 h[4];
    h[0] = __floats2half2_rn(a.x, a.y);
    h[1] = __floats2half2_rn(a.z, a.w);
    h[2] = __floats2half2_rn(b.x, b.y);
    h[3] = __floats2half2_rn(b.z, b.w);
    *(uint4*)&g_wh[idx] = *(uint4*)h;
}

// ---------------- 3) SpMM fp16: agg[i,:] = norm_i * sum_j norm_j * feat[j,:] ----------------
// blockDim = (C/8, 128/(C/8)); each thread handles 8 halves (one uint4).
template <int C>
__global__ void spmm_fp16(const __half* __restrict__ feat, __half* __restrict__ agg) {
    constexpr int TX = C / 8;
    constexpr int TY = 128 / TX;
    int y = threadIdx.y;
    int i = blockIdx.x * TY + y;
    __shared__ int   sc[TY][SLOTS];
    __shared__ float sw[TY][SLOTS];
    int d = g_deg[i];
    for (int k = threadIdx.x; k < d; k += TX) {
        int j = g_col[i * SLOTS + k];
        sc[y][k] = j;
        sw[y][k] = g_norm[j];
    }
    __syncthreads();
    int c8 = threadIdx.x * 8;
    float acc[8] = {0.f, 0.f, 0.f, 0.f, 0.f, 0.f, 0.f, 0.f};
    for (int k = 0; k < d; k++) {
        float w = sw[y][k];
        uint4 v = *(const uint4*)&feat[(size_t)sc[y][k] * C + c8];
        const __half2* hv = (const __half2*)&v;
#pragma unroll
        for (int q = 0; q < 4; q++) {
            float2 f = __half22float2(hv[q]);
            acc[q * 2 + 0] = fmaf(w, f.x, acc[q * 2 + 0]);
            acc[q * 2 + 1] = fmaf(w, f.y, acc[q * 2 + 1]);
        }
    }
    float ni = g_norm[i];
    __half2 ho[4];
#pragma unroll
    for (int q = 0; q < 4; q++)
        ho[q] = __floats2half2_rn(acc[q * 2] * ni, acc[q * 2 + 1] * ni);
    *(uint4*)&agg[(size_t)i * C + c8] = *(uint4*)ho;
}

// ---------------- 4) fp16 tensor GEMM + bias + softplus ----------------
__device__ __forceinline__ void mma_f16(float* d, const uint32_t* a, const uint32_t* b) {
    asm volatile(
        "mma.sync.aligned.m16n8k16.row.col.f32.f16.f16.f32 "
        "{%0,%1,%2,%3}, {%4,%5,%6,%7}, {%8,%9}, {%0,%1,%2,%3};\n"
        : "+f"(d[0]), "+f"(d[1]), "+f"(d[2]), "+f"(d[3])
        : "r"(a[0]), "r"(a[1]), "r"(a[2]), "r"(a[3]), "r"(b[0]), "r"(b[1]));
}

__device__ __forceinline__ void ldmat_x4(uint32_t* r, uint32_t saddr) {
    asm volatile(
        "ldmatrix.sync.aligned.m8n8.x4.shared.b16 {%0,%1,%2,%3}, [%4];\n"
        : "=r"(r[0]), "=r"(r[1]), "=r"(r[2]), "=r"(r[3])
        : "r"(saddr));
}

__device__ __forceinline__ void ldmat_x4_trans(uint32_t* r, uint32_t saddr) {
    asm volatile(
        "ldmatrix.sync.aligned.m8n8.x4.trans.shared.b16 {%0,%1,%2,%3}, [%4];\n"
        : "=r"(r[0]), "=r"(r[1]), "=r"(r[2]), "=r"(r[3])
        : "r"(saddr));
}

// Block tile 128x128, BK=32 (fp16), 8 warps (2x4), warp tile 64x32.
// A smem [m][k] LDA=40 halves; B smem [k][n] LDB=136 halves. All ldmatrix paths
// and STS.128 store phases verified bank-conflict-free.
template <int K, bool OUT_HALF>
__global__ __launch_bounds__(256, 2) void gemm_f16_softplus(
    const __half* __restrict__ A,
    const __half* __restrict__ Bh,
    const float* __restrict__ bias,
    void* __restrict__ CoutV)
{
    constexpr int BM = 128, BN = 128, BK = 32;
    constexpr int LDA = BK + 8;   // 40 halves (80B; rows 0..7 -> distinct bank quads)
    constexpr int LDB = BN + 8;   // 136 halves (272B; k-rows stride 4 banks)

    __shared__ __align__(16) __half As[2][BM][LDA];  // 20 KB
    __shared__ __align__(16) __half Bs[2][BK][LDB];  // 17 KB

    int tid  = threadIdx.x;
    int lane = tid & 31;
    int warp = tid >> 5;
    int g    = lane >> 2;
    int tg   = lane & 3;
    int wm   = (warp & 1) * 64;
    int wn   = (warp >> 1) * 32;
    int m0   = blockIdx.y * BM;
    int n0   = blockIdx.x * BN;

    int lmrow = lane & 15;
    int lmhi  = (lane >> 4) * 8;

    float acc[4][4][4];
#pragma unroll
    for (int i = 0; i < 4; i++)
#pragma unroll
        for (int j = 0; j < 4; j++)
#pragma unroll
            for (int r = 0; r < 4; r++) acc[i][j][r] = 0.0f;

    // global staging regs
    uint4 pa[2], pb[2];
    // A mapping: i in {0,1}: row = tid&127, col8 = ((tid>>7)*2 + i)*8
    int a_row = tid & 127;
    int a_c0  = ((tid >> 7) * 2) * 8;
    // B mapping: f = i*256 + tid: row = f>>4, col8 = (f&15)*8

    auto loadg = [&](int k0) {
#pragma unroll
        for (int i = 0; i < 2; i++) {
            pa[i] = *(const uint4*)&A[(size_t)(m0 + a_row) * K + k0 + a_c0 + i * 8];
            int f  = i * 256 + tid;
            int rb = f >> 4, cb = (f & 15) * 8;
            pb[i] = *(const uint4*)&Bh[(size_t)(k0 + rb) * HID + n0 + cb];
        }
    };
    auto stores = [&](int buf) {
#pragma unroll
        for (int i = 0; i < 2; i++) {
            *(uint4*)&As[buf][a_row][a_c0 + i * 8] = pa[i];
            int f  = i * 256 + tid;
            int rb = f >> 4, cb = (f & 15) * 8;
            *(uint4*)&Bs[buf][rb][cb] = pb[i];
        }
    };
    auto compute = [&](int buf) {
#pragma unroll
        for (int ks = 0; ks < BK; ks += 16) {
            uint32_t a[4][4], b[4][2];
#pragma unroll
            for (int i = 0; i < 4; i++) {
                uint32_t saddr = (uint32_t)__cvta_generic_to_shared(
                    &As[buf][wm + i * 16 + lmrow][ks + lmhi]);
                ldmat_x4(a[i], saddr);
            }
#pragma unroll
            for (int jj = 0; jj < 2; jj++) {
                uint32_t r[4];
                uint32_t saddr = (uint32_t)__cvta_generic_to_shared(
                    &Bs[buf][ks + lmrow][wn + jj * 16 + lmhi]);
                ldmat_x4_trans(r, saddr);
                b[jj * 2 + 0][0] = r[0]; b[jj * 2 + 0][1] = r[1];
                b[jj * 2 + 1][0] = r[2]; b[jj * 2 + 1][1] = r[3];
            }
#pragma unroll
            for (int i = 0; i < 4; i++)
#pragma unroll
                for (int j = 0; j < 4; j++)
                    mma_f16(acc[i][j], a[i], b[j]);
        }
    };

    constexpr int NK = K / BK;
    loadg(0);
    stores(0);
    __syncthreads();
#pragma unroll 1
    for (int t = 0; t < NK; t++) {
        if (t + 1 < NK) loadg((t + 1) * BK);
        compute(t & 1);
        if (t + 1 < NK) {
            stores((t + 1) & 1);
            __syncthreads();
        }
    }

    // epilogue: bias + fast stable softplus
#pragma unroll
    for (int i = 0; i < 4; i++) {
        int row = m0 + wm + i * 16 + g;
#pragma unroll
        for (int j = 0; j < 4; j++) {
            int col = n0 + wn + j * 8 + tg * 2;
            float bx = bias[col], by = bias[col + 1];
            float x0 = acc[i][j][0] + bx;
            float x1 = acc[i][j][1] + by;
            float x2 = acc[i][j][2] + bx;
            float x3 = acc[i][j][3] + by;
            float s0 = fmaxf(x0, 0.f) + __logf(1.0f + __expf(-fabsf(x0)));
            float s1 = fmaxf(x1, 0.f) + __logf(1.0f + __expf(-fabsf(x1)));
            float s2 = fmaxf(x2, 0.f) + __logf(1.0f + __expf(-fabsf(x2)));
            float s3 = fmaxf(x3, 0.f) + __logf(1.0f + __expf(-fabsf(x3)));
            if (OUT_HALF) {
                __half* C = (__half*)CoutV;
                *(__half2*)&C[(size_t)row * HID + col]       = __floats2half2_rn(s0, s1);
                *(__half2*)&C[(size_t)(row + 8) * HID + col] = __floats2half2_rn(s2, s3);
            } else {
                float* C = (float*)CoutV;
                *(float2*)&C[(size_t)row * HID + col]       = make_float2(s0, s1);
                *(float2*)&C[(size_t)(row + 8) * HID + col] = make_float2(s2, s3);
            }
        }
    }
}

// ---------------- launch ----------------
extern "C" void kernel_launch(void* const* d_in, const int* in_sizes, int n_in,
                              void* d_out, int out_size) {
    const float* atom_pos = (const float*)d_in[0];
    const float* dist_adj = (const float*)d_in[1];
    const float* atom_emb = (const float*)d_in[2];
    const float* W0 = (const float*)d_in[3];
    const float* b0 = (const float*)d_in[4];
    const float* W1 = (const float*)d_in[5];
    const float* b1 = (const float*)d_in[6];
    const float* W2 = (const float*)d_in[7];
    const float* b2 = (const float*)d_in[8];
    const float* W3 = (const float*)d_in[9];
    const float* b3 = (const float*)d_in[10];
    float* out = (float*)d_out;

    __half *bufA, *bufB, *wh;
    cudaGetSymbolAddress((void**)&bufA, g_hbufA);
    cudaGetSymbolAddress((void**)&bufB, g_hbufB);
    cudaGetSymbolAddress((void**)&wh,   g_wh);

    const __half* WH0 = wh;
    const __half* WH1 = wh + W0_ELEMS;
    const __half* WH2 = wh + W0_ELEMS + W_ELEMS;
    const __half* WH3 = wh + W0_ELEMS + 2 * W_ELEMS;

    build_kernel<<<NN / 8, 256>>>(dist_adj);
    concat_kernel<<<(NN * FIN + 255) / 256, 256>>>(atom_emb, atom_pos, bufA);
    wconv_kernel<<<(WH_TOTAL / 8 + 255) / 256, 256>>>(W0, W1, W2, W3);

    dim3 ggrid(HID / 128, NN / 128);   // (4, 64)

    // Layer 0: K = FIN = 128
    spmm_fp16<FIN><<<NN / 8, dim3(16, 8)>>>(bufA, bufB);
    gemm_f16_softplus<FIN, true><<<ggrid, 256>>>(bufB, WH0, b0, bufA);

    // Layer 1
    spmm_fp16<HID><<<NN / 2, dim3(64, 2)>>>(bufA, bufB);
    gemm_f16_softplus<HID, true><<<ggrid, 256>>>(bufB, WH1, b1, bufA);

    // Layer 2
    spmm_fp16<HID><<<NN / 2, dim3(64, 2)>>>(bufA, bufB);
    gemm_f16_softplus<HID, true><<<ggrid, 256>>>(bufB, WH2, b2, bufA);

    // Layer 3 -> fp32 to d_out
    spmm_fp16<HID><<<NN / 2, dim3(64, 2)>>>(bufA, bufB);
    gemm_f16_softplus<HID, false><<<ggrid, 256>>>(bufB, WH3, b3, out);
}

// round 13
// speedup vs baseline: 1.0017x; 1.0011x over previous
#include <cuda_runtime.h>
#include <cuda_fp16.h>
#include <math.h>
#include <stdint.h>

// Problem constants (fixed by reference)
#define NN   8192
#define EMB  125
#define POSD 3
#define FIN  128     // EMB + POSD
#define HID  512
#define SLOTS 256

#define W0_ELEMS (FIN * HID)          // 65536
#define W_ELEMS  (HID * HID)          // 262144
#define WH_TOTAL (W0_ELEMS + 3 * W_ELEMS)  // 851968

// ---------------- device scratch (no allocation allowed) ----------------
__device__ int   g_col[NN * SLOTS];
__device__ int   g_deg[NN];
__device__ float g_norm[NN];
__device__ __align__(16) __half g_hbufA[NN * HID];   // 8 MB
__device__ __align__(16) __half g_hbufB[NN * HID];   // 8 MB
__device__ __align__(16) __half g_wh[WH_TOTAL];      // 1.7 MB fp16 weights

// ---------------- 1) build sparse structure + norms ----------------
__global__ void build_kernel(const float* __restrict__ adj) {
    int warp = threadIdx.x >> 5;
    int lane = threadIdx.x & 31;
    int row  = blockIdx.x * (blockDim.x >> 5) + warp;
    if (row >= NN) return;

    const float* arow = adj + (size_t)row * NN;
    int cnt = 0;
    for (int c0 = 0; c0 < NN; c0 += 32) {
        int c = c0 + lane;
        float v = arow[c];
        bool pred = (v != 0.0f) && (c != row);
        unsigned mask = __ballot_sync(0xFFFFFFFFu, pred);
        int pos = cnt + __popc(mask & ((1u << lane) - 1u));
        if (pred && pos < SLOTS) g_col[row * SLOTS + pos] = c;
        cnt += __popc(mask);
    }
    if (lane == 0) {
        g_deg[row]  = (cnt < SLOTS) ? cnt : SLOTS;
        g_norm[row] = rsqrtf(fmaxf((float)cnt, 1.0f));
    }
}

// ---------------- 2) concat emb||pos -> fp16 feat [NN, FIN] ----------------
__global__ void concat_kernel(const float* __restrict__ emb,
                              const float* __restrict__ pos,
                              __half* __restrict__ out) {
    int idx = blockIdx.x * blockDim.x + threadIdx.x;
    if (idx >= NN * FIN) return;
    int i = idx / FIN, c = idx % FIN;
    float v = (c < EMB) ? emb[i * EMB + c] : pos[i * POSD + (c - EMB)];
    out[idx] = __float2half(v);
}

// ---------------- 2b) convert weights to fp16 (compact layout) ----------------
__global__ void wconv_kernel(const float* __restrict__ W0, const float* __restrict__ W1,
                             const float* __restrict__ W2, const float* __restrict__ W3) {
    int idx = (blockIdx.x * blockDim.x + threadIdx.x) * 8;
    if (idx >= WH_TOTAL) return;
    const float* src;
    if (idx < W0_ELEMS)                    src = W0 + idx;
    else if (idx < W0_ELEMS + W_ELEMS)     src = W1 + (idx - W0_ELEMS);
    else if (idx < W0_ELEMS + 2 * W_ELEMS) src = W2 + (idx - W0_ELEMS - W_ELEMS);
    else                                   src = W3 + (idx - W0_ELEMS - 2 * W_ELEMS);
    float4 a = *(const float4*)src;
    float4 b = *(const float4*)(src + 4);
    __half2 h[4];
    h[0] = __floats2half2_rn(a.x, a.y);
    h[1] = __floats2half2_rn(a.z, a.w);
    h[2] = __floats2half2_rn(b.x, b.y);
    h[3] = __floats2half2_rn(b.z, b.w);
    *(uint4*)&g_wh[idx] = *(uint4*)h;
}

// ---------------- 3) SpMM fp16: agg[i,:] = norm_i * sum_j norm_j * feat[j,:] ----------------
// blockDim = (C/8, 128/(C/8)); each thread handles 8 halves (one uint4).
template <int C>
__global__ void spmm_fp16(const __half* __restrict__ feat, __half* __restrict__ agg) {
    constexpr int TX = C / 8;
    constexpr int TY = 128 / TX;
    int y = threadIdx.y;
    int i = blockIdx.x * TY + y;
    __shared__ int   sc[TY][SLOTS];
    __shared__ float sw[TY][SLOTS];
    int d = g_deg[i];
    for (int k = threadIdx.x; k < d; k += TX) {
        int j = g_col[i * SLOTS + k];
        sc[y][k] = j;
        sw[y][k] = g_norm[j];
    }
    __syncthreads();
    int c8 = threadIdx.x * 8;
    float acc[8] = {0.f, 0.f, 0.f, 0.f, 0.f, 0.f, 0.f, 0.f};
    for (int k = 0; k < d; k++) {
        float w = sw[y][k];
        uint4 v = *(const uint4*)&feat[(size_t)sc[y][k] * C + c8];
        const __half2* hv = (const __half2*)&v;
#pragma unroll
        for (int q = 0; q < 4; q++) {
            float2 f = __half22float2(hv[q]);
            acc[q * 2 + 0] = fmaf(w, f.x, acc[q * 2 + 0]);
            acc[q * 2 + 1] = fmaf(w, f.y, acc[q * 2 + 1]);
        }
    }
    float ni = g_norm[i];
    __half2 ho[4];
#pragma unroll
    for (int q = 0; q < 4; q++)
        ho[q] = __floats2half2_rn(acc[q * 2] * ni, acc[q * 2 + 1] * ni);
    *(uint4*)&agg[(size_t)i * C + c8] = *(uint4*)ho;
}

// ---------------- 4) fp16 tensor GEMM + bias + softplus ----------------
__device__ __forceinline__ void mma_f16(float* d, const uint32_t* a, const uint32_t* b) {
    asm volatile(
        "mma.sync.aligned.m16n8k16.row.col.f32.f16.f16.f32 "
        "{%0,%1,%2,%3}, {%4,%5,%6,%7}, {%8,%9}, {%0,%1,%2,%3};\n"
        : "+f"(d[0]), "+f"(d[1]), "+f"(d[2]), "+f"(d[3])
        : "r"(a[0]), "r"(a[1]), "r"(a[2]), "r"(a[3]), "r"(b[0]), "r"(b[1]));
}

__device__ __forceinline__ void ldmat_x4(uint32_t* r, uint32_t saddr) {
    asm volatile(
        "ldmatrix.sync.aligned.m8n8.x4.shared.b16 {%0,%1,%2,%3}, [%4];\n"
        : "=r"(r[0]), "=r"(r[1]), "=r"(r[2]), "=r"(r[3])
        : "r"(saddr));
}

__device__ __forceinline__ void ldmat_x4_trans(uint32_t* r, uint32_t saddr) {
    asm volatile(
        "ldmatrix.sync.aligned.m8n8.x4.trans.shared.b16 {%0,%1,%2,%3}, [%4];\n"
        : "=r"(r[0]), "=r"(r[1]), "=r"(r[2]), "=r"(r[3])
        : "r"(saddr));
}

// Block tile 128x128, BK=32 (fp16), 8 warps (2x4), warp tile 64x32.
// A smem [m][k] LDA=40 halves; B smem [k][n] LDB=136 halves. All ldmatrix paths
// and STS.128 store phases verified bank-conflict-free.
template <int K, bool OUT_HALF>
__global__ __launch_bounds__(256, 2) void gemm_f16_softplus(
    const __half* __restrict__ A,
    const __half* __restrict__ Bh,
    const float* __restrict__ bias,
    void* __restrict__ CoutV)
{
    constexpr int BM = 128, BN = 128, BK = 32;
    constexpr int LDA = BK + 8;   // 40 halves (80B; rows 0..7 -> distinct bank quads)
    constexpr int LDB = BN + 8;   // 136 halves (272B; k-rows stride 4 banks)

    __shared__ __align__(16) __half As[2][BM][LDA];  // 20 KB
    __shared__ __align__(16) __half Bs[2][BK][LDB];  // 17 KB

    int tid  = threadIdx.x;
    int lane = tid & 31;
    int warp = tid >> 5;
    int g    = lane >> 2;
    int tg   = lane & 3;
    int wm   = (warp & 1) * 64;
    int wn   = (warp >> 1) * 32;
    int m0   = blockIdx.y * BM;
    int n0   = blockIdx.x * BN;

    int lmrow = lane & 15;
    int lmhi  = (lane >> 4) * 8;

    float acc[4][4][4];
#pragma unroll
    for (int i = 0; i < 4; i++)
#pragma unroll
        for (int j = 0; j < 4; j++)
#pragma unroll
            for (int r = 0; r < 4; r++) acc[i][j][r] = 0.0f;

    // global staging regs
    uint4 pa[2], pb[2];
    // A mapping: i in {0,1}: row = tid&127, col8 = ((tid>>7)*2 + i)*8
    int a_row = tid & 127;
    int a_c0  = ((tid >> 7) * 2) * 8;
    // B mapping: f = i*256 + tid: row = f>>4, col8 = (f&15)*8

    auto loadg = [&](int k0) {
#pragma unroll
        for (int i = 0; i < 2; i++) {
            pa[i] = *(const uint4*)&A[(size_t)(m0 + a_row) * K + k0 + a_c0 + i * 8];
            int f  = i * 256 + tid;
            int rb = f >> 4, cb = (f & 15) * 8;
            pb[i] = *(const uint4*)&Bh[(size_t)(k0 + rb) * HID + n0 + cb];
        }
    };
    auto stores = [&](int buf) {
#pragma unroll
        for (int i = 0; i < 2; i++) {
            *(uint4*)&As[buf][a_row][a_c0 + i * 8] = pa[i];
            int f  = i * 256 + tid;
            int rb = f >> 4, cb = (f & 15) * 8;
            *(uint4*)&Bs[buf][rb][cb] = pb[i];
        }
    };
    auto compute = [&](int buf) {
#pragma unroll
        for (int ks = 0; ks < BK; ks += 16) {
            uint32_t a[4][4], b[4][2];
#pragma unroll
            for (int i = 0; i < 4; i++) {
                uint32_t saddr = (uint32_t)__cvta_generic_to_shared(
                    &As[buf][wm + i * 16 + lmrow][ks + lmhi]);
                ldmat_x4(a[i], saddr);
            }
#pragma unroll
            for (int jj = 0; jj < 2; jj++) {
                uint32_t r[4];
                uint32_t saddr = (uint32_t)__cvta_generic_to_shared(
                    &Bs[buf][ks + lmrow][wn + jj * 16 + lmhi]);
                ldmat_x4_trans(r, saddr);
                b[jj * 2 + 0][0] = r[0]; b[jj * 2 + 0][1] = r[1];
                b[jj * 2 + 1][0] = r[2]; b[jj * 2 + 1][1] = r[3];
            }
#pragma unroll
            for (int i = 0; i < 4; i++)
#pragma unroll
                for (int j = 0; j < 4; j++)
                    mma_f16(acc[i][j], a[i], b[j]);
        }
    };

    constexpr int NK = K / BK;
    loadg(0);
    stores(0);
    __syncthreads();
#pragma unroll 1
    for (int t = 0; t < NK; t++) {
        if (t + 1 < NK) loadg((t + 1) * BK);
        compute(t & 1);
        if (t + 1 < NK) {
            stores((t + 1) & 1);
            __syncthreads();
        }
    }

    // epilogue: bias + fast stable softplus
#pragma unroll
    for (int i = 0; i < 4; i++) {
        int row = m0 + wm + i * 16 + g;
#pragma unroll
        for (int j = 0; j < 4; j++) {
            int col = n0 + wn + j * 8 + tg * 2;
            float bx = bias[col], by = bias[col + 1];
            float x0 = acc[i][j][0] + bx;
            float x1 = acc[i][j][1] + by;
            float x2 = acc[i][j][2] + bx;
            float x3 = acc[i][j][3] + by;
            float s0 = fmaxf(x0, 0.f) + __logf(1.0f + __expf(-fabsf(x0)));
            float s1 = fmaxf(x1, 0.f) + __logf(1.0f + __expf(-fabsf(x1)));
            float s2 = fmaxf(x2, 0.f) + __logf(1.0f + __expf(-fabsf(x2)));
            float s3 = fmaxf(x3, 0.f) + __logf(1.0f + __expf(-fabsf(x3)));
            if (OUT_HALF) {
                __half* C = (__half*)CoutV;
                *(__half2*)&C[(size_t)row * HID + col]       = __floats2half2_rn(s0, s1);
                *(__half2*)&C[(size_t)(row + 8) * HID + col] = __floats2half2_rn(s2, s3);
            } else {
                float* C = (float*)CoutV;
                *(float2*)&C[(size_t)row * HID + col]       = make_float2(s0, s1);
                *(float2*)&C[(size_t)(row + 8) * HID + col] = make_float2(s2, s3);
            }
        }
    }
}

// ---------------- launch ----------------
extern "C" void kernel_launch(void* const* d_in, const int* in_sizes, int n_in,
                              void* d_out, int out_size) {
    const float* atom_pos = (const float*)d_in[0];
    const float* dist_adj = (const float*)d_in[1];
    const float* atom_emb = (const float*)d_in[2];
    const float* W0 = (const float*)d_in[3];
    const float* b0 = (const float*)d_in[4];
    const float* W1 = (const float*)d_in[5];
    const float* b1 = (const float*)d_in[6];
    const float* W2 = (const float*)d_in[7];
    const float* b2 = (const float*)d_in[8];
    const float* W3 = (const float*)d_in[9];
    const float* b3 = (const float*)d_in[10];
    float* out = (float*)d_out;

    __half *bufA, *bufB, *wh;
    cudaGetSymbolAddress((void**)&bufA, g_hbufA);
    cudaGetSymbolAddress((void**)&bufB, g_hbufB);
    cudaGetSymbolAddress((void**)&wh,   g_wh);

    const __half* WH0 = wh;
    const __half* WH1 = wh + W0_ELEMS;
    const __half* WH2 = wh + W0_ELEMS + W_ELEMS;
    const __half* WH3 = wh + W0_ELEMS + 2 * W_ELEMS;

    build_kernel<<<NN / 8, 256>>>(dist_adj);
    concat_kernel<<<(NN * FIN + 255) / 256, 256>>>(atom_emb, atom_pos, bufA);
    wconv_kernel<<<(WH_TOTAL / 8 + 255) / 256, 256>>>(W0, W1, W2, W3);

    dim3 ggrid(HID / 128, NN / 128);   // (4, 64)

    // Layer 0: K = FIN = 128
    spmm_fp16<FIN><<<NN / 8, dim3(16, 8)>>>(bufA, bufB);
    gemm_f16_softplus<FIN, true><<<ggrid, 256>>>(bufB, WH0, b0, bufA);

    // Layer 1
    spmm_fp16<HID><<<NN / 2, dim3(64, 2)>>>(bufA, bufB);
    gemm_f16_softplus<HID, true><<<ggrid, 256>>>(bufB, WH1, b1, bufA);

    // Layer 2
    spmm_fp16<HID><<<NN / 2, dim3(64, 2)>>>(bufA, bufB);
    gemm_f16_softplus<HID, true><<<ggrid, 256>>>(bufB, WH2, b2, bufA);

    // Layer 3 -> fp32 to d_out
    spmm_fp16<HID><<<NN / 2, dim3(64, 2)>>>(bufA, bufB);
    gemm_f16_softplus<HID, false><<<ggrid, 256>>>(bufB, WH3, b3, out);
}

// round 14
// speedup vs baseline: 1.0018x; 1.0001x over previous
#include <cuda_runtime.h>
#include <cuda_fp16.h>
#include <math.h>
#include <stdint.h>

// Problem constants (fixed by reference)
#define NN   8192
#define EMB  125
#define POSD 3
#define FIN  128     // EMB + POSD
#define HID  512
#define SLOTS 256

#define W0_ELEMS (FIN * HID)          // 65536
#define W_ELEMS  (HID * HID)          // 262144
#define WH_TOTAL (W0_ELEMS + 3 * W_ELEMS)  // 851968

// ---------------- device scratch (no allocation allowed) ----------------
__device__ int   g_col[NN * SLOTS];
__device__ int   g_deg[NN];
__device__ float g_norm[NN];
__device__ __align__(16) __half g_hbufA[NN * HID];   // 8 MB
__device__ __align__(16) __half g_hbufB[NN * HID];   // 8 MB
__device__ __align__(16) __half g_wh[WH_TOTAL];      // 1.7 MB fp16 weights

// ---------------- 1) build sparse structure + norms ----------------
__global__ void build_kernel(const float* __restrict__ adj) {
    int warp = threadIdx.x >> 5;
    int lane = threadIdx.x & 31;
    int row  = blockIdx.x * (blockDim.x >> 5) + warp;
    if (row >= NN) return;

    const float* arow = adj + (size_t)row * NN;
    int cnt = 0;
    for (int c0 = 0; c0 < NN; c0 += 32) {
        int c = c0 + lane;
        float v = arow[c];
        bool pred = (v != 0.0f) && (c != row);
        unsigned mask = __ballot_sync(0xFFFFFFFFu, pred);
        int pos = cnt + __popc(mask & ((1u << lane) - 1u));
        if (pred && pos < SLOTS) g_col[row * SLOTS + pos] = c;
        cnt += __popc(mask);
    }
    if (lane == 0) {
        g_deg[row]  = (cnt < SLOTS) ? cnt : SLOTS;
        g_norm[row] = rsqrtf(fmaxf((float)cnt, 1.0f));
    }
}

// ---------------- 2) concat emb||pos -> fp16 feat [NN, FIN] ----------------
__global__ void concat_kernel(const float* __restrict__ emb,
                              const float* __restrict__ pos,
                              __half* __restrict__ out) {
    int idx = blockIdx.x * blockDim.x + threadIdx.x;
    if (idx >= NN * FIN) return;
    int i = idx / FIN, c = idx % FIN;
    float v = (c < EMB) ? emb[i * EMB + c] : pos[i * POSD + (c - EMB)];
    out[idx] = __float2half(v);
}

// ---------------- 2b) convert weights to fp16 (compact layout) ----------------
__global__ void wconv_kernel(const float* __restrict__ W0, const float* __restrict__ W1,
                             const float* __restrict__ W2, const float* __restrict__ W3) {
    int idx = (blockIdx.x * blockDim.x + threadIdx.x) * 8;
    if (idx >= WH_TOTAL) return;
    const float* src;
    if (idx < W0_ELEMS)                    src = W0 + idx;
    else if (idx < W0_ELEMS + W_ELEMS)     src = W1 + (idx - W0_ELEMS);
    else if (idx < W0_ELEMS + 2 * W_ELEMS) src = W2 + (idx - W0_ELEMS - W_ELEMS);
    else                                   src = W3 + (idx - W0_ELEMS - 2 * W_ELEMS);
    float4 a = *(const float4*)src;
    float4 b = *(const float4*)(src + 4);
    __half2 h[4];
    h[0] = __floats2half2_rn(a.x, a.y);
    h[1] = __floats2half2_rn(a.z, a.w);
    h[2] = __floats2half2_rn(b.x, b.y);
    h[3] = __floats2half2_rn(b.z, b.w);
    *(uint4*)&g_wh[idx] = *(uint4*)h;
}

// ---------------- 3) SpMM fp16: agg[i,:] = norm_i * sum_j norm_j * feat[j,:] ----------------
// blockDim = (C/8, 128/(C/8)); each thread handles 8 halves (one uint4).
template <int C>
__global__ void spmm_fp16(const __half* __restrict__ feat, __half* __restrict__ agg) {
    constexpr int TX = C / 8;
    constexpr int TY = 128 / TX;
    int y = threadIdx.y;
    int i = blockIdx.x * TY + y;
    __shared__ int   sc[TY][SLOTS];
    __shared__ float sw[TY][SLOTS];
    int d = g_deg[i];
    for (int k = threadIdx.x; k < d; k += TX) {
        int j = g_col[i * SLOTS + k];
        sc[y][k] = j;
        sw[y][k] = g_norm[j];
    }
    __syncthreads();
    int c8 = threadIdx.x * 8;
    float acc[8] = {0.f, 0.f, 0.f, 0.f, 0.f, 0.f, 0.f, 0.f};
    for (int k = 0; k < d; k++) {
        float w = sw[y][k];
        uint4 v = *(const uint4*)&feat[(size_t)sc[y][k] * C + c8];
        const __half2* hv = (const __half2*)&v;
#pragma unroll
        for (int q = 0; q < 4; q++) {
            float2 f = __half22float2(hv[q]);
            acc[q * 2 + 0] = fmaf(w, f.x, acc[q * 2 + 0]);
            acc[q * 2 + 1] = fmaf(w, f.y, acc[q * 2 + 1]);
        }
    }
    float ni = g_norm[i];
    __half2 ho[4];
#pragma unroll
    for (int q = 0; q < 4; q++)
        ho[q] = __floats2half2_rn(acc[q * 2] * ni, acc[q * 2 + 1] * ni);
    *(uint4*)&agg[(size_t)i * C + c8] = *(uint4*)ho;
}

// ---------------- 4) fp16 tensor GEMM + bias + softplus ----------------
__device__ __forceinline__ void mma_f16(float* d, const uint32_t* a, const uint32_t* b) {
    asm volatile(
        "mma.sync.aligned.m16n8k16.row.col.f32.f16.f16.f32 "
        "{%0,%1,%2,%3}, {%4,%5,%6,%7}, {%8,%9}, {%0,%1,%2,%3};\n"
        : "+f"(d[0]), "+f"(d[1]), "+f"(d[2]), "+f"(d[3])
        : "r"(a[0]), "r"(a[1]), "r"(a[2]), "r"(a[3]), "r"(b[0]), "r"(b[1]));
}

__device__ __forceinline__ void ldmat_x4(uint32_t* r, uint32_t saddr) {
    asm volatile(
        "ldmatrix.sync.aligned.m8n8.x4.shared.b16 {%0,%1,%2,%3}, [%4];\n"
        : "=r"(r[0]), "=r"(r[1]), "=r"(r[2]), "=r"(r[3])
        : "r"(saddr));
}

__device__ __forceinline__ void ldmat_x4_trans(uint32_t* r, uint32_t saddr) {
    asm volatile(
        "ldmatrix.sync.aligned.m8n8.x4.trans.shared.b16 {%0,%1,%2,%3}, [%4];\n"
        : "=r"(r[0]), "=r"(r[1]), "=r"(r[2]), "=r"(r[3])
        : "r"(saddr));
}

// Block tile 128x128, BK=32 (fp16), 8 warps (2x4), warp tile 64x32.
// A smem [m][k] LDA=40 halves; B smem [k][n] LDB=136 halves. All ldmatrix paths
// and STS.128 store phases verified bank-conflict-free.
template <int K, bool OUT_HALF>
__global__ __launch_bounds__(256, 2) void gemm_f16_softplus(
    const __half* __restrict__ A,
    const __half* __restrict__ Bh,
    const float* __restrict__ bias,
    void* __restrict__ CoutV)
{
    constexpr int BM = 128, BN = 128, BK = 32;
    constexpr int LDA = BK + 8;   // 40 halves (80B; rows 0..7 -> distinct bank quads)
    constexpr int LDB = BN + 8;   // 136 halves (272B; k-rows stride 4 banks)

    __shared__ __align__(16) __half As[2][BM][LDA];  // 20 KB
    __shared__ __align__(16) __half Bs[2][BK][LDB];  // 17 KB

    int tid  = threadIdx.x;
    int lane = tid & 31;
    int warp = tid >> 5;
    int g    = lane >> 2;
    int tg   = lane & 3;
    int wm   = (warp & 1) * 64;
    int wn   = (warp >> 1) * 32;
    int m0   = blockIdx.y * BM;
    int n0   = blockIdx.x * BN;

    int lmrow = lane & 15;
    int lmhi  = (lane >> 4) * 8;

    float acc[4][4][4];
#pragma unroll
    for (int i = 0; i < 4; i++)
#pragma unroll
        for (int j = 0; j < 4; j++)
#pragma unroll
            for (int r = 0; r < 4; r++) acc[i][j][r] = 0.0f;

    // global staging regs
    uint4 pa[2], pb[2];
    // A mapping: i in {0,1}: row = tid&127, col8 = ((tid>>7)*2 + i)*8
    int a_row = tid & 127;
    int a_c0  = ((tid >> 7) * 2) * 8;
    // B mapping: f = i*256 + tid: row = f>>4, col8 = (f&15)*8

    auto loadg = [&](int k0) {
#pragma unroll
        for (int i = 0; i < 2; i++) {
            pa[i] = *(const uint4*)&A[(size_t)(m0 + a_row) * K + k0 + a_c0 + i * 8];
            int f  = i * 256 + tid;
            int rb = f >> 4, cb = (f & 15) * 8;
            pb[i] = *(const uint4*)&Bh[(size_t)(k0 + rb) * HID + n0 + cb];
        }
    };
    auto stores = [&](int buf) {
#pragma unroll
        for (int i = 0; i < 2; i++) {
            *(uint4*)&As[buf][a_row][a_c0 + i * 8] = pa[i];
            int f  = i * 256 + tid;
            int rb = f >> 4, cb = (f & 15) * 8;
            *(uint4*)&Bs[buf][rb][cb] = pb[i];
        }
    };
    auto compute = [&](int buf) {
#pragma unroll
        for (int ks = 0; ks < BK; ks += 16) {
            uint32_t a[4][4], b[4][2];
#pragma unroll
            for (int i = 0; i < 4; i++) {
                uint32_t saddr = (uint32_t)__cvta_generic_to_shared(
                    &As[buf][wm + i * 16 + lmrow][ks + lmhi]);
                ldmat_x4(a[i], saddr);
            }
#pragma unroll
            for (int jj = 0; jj < 2; jj++) {
                uint32_t r[4];
                uint32_t saddr = (uint32_t)__cvta_generic_to_shared(
                    &Bs[buf][ks + lmrow][wn + jj * 16 + lmhi]);
                ldmat_x4_trans(r, saddr);
                b[jj * 2 + 0][0] = r[0]; b[jj * 2 + 0][1] = r[1];
                b[jj * 2 + 1][0] = r[2]; b[jj * 2 + 1][1] = r[3];
            }
#pragma unroll
            for (int i = 0; i < 4; i++)
#pragma unroll
                for (int j = 0; j < 4; j++)
                    mma_f16(acc[i][j], a[i], b[j]);
        }
    };

    constexpr int NK = K / BK;
    loadg(0);
    stores(0);
    __syncthreads();
#pragma unroll 1
    for (int t = 0; t < NK; t++) {
        if (t + 1 < NK) loadg((t + 1) * BK);
        compute(t & 1);
        if (t + 1 < NK) {
            stores((t + 1) & 1);
            __syncthreads();
        }
    }

    // epilogue: bias + fast stable softplus
#pragma unroll
    for (int i = 0; i < 4; i++) {
        int row = m0 + wm + i * 16 + g;
#pragma unroll
        for (int j = 0; j < 4; j++) {
            int col = n0 + wn + j * 8 + tg * 2;
            float bx = bias[col], by = bias[col + 1];
            float x0 = acc[i][j][0] + bx;
            float x1 = acc[i][j][1] + by;
            float x2 = acc[i][j][2] + bx;
            float x3 = acc[i][j][3] + by;
            float s0 = fmaxf(x0, 0.f) + __logf(1.0f + __expf(-fabsf(x0)));
            float s1 = fmaxf(x1, 0.f) + __logf(1.0f + __expf(-fabsf(x1)));
            float s2 = fmaxf(x2, 0.f) + __logf(1.0f + __expf(-fabsf(x2)));
            float s3 = fmaxf(x3, 0.f) + __logf(1.0f + __expf(-fabsf(x3)));
            if (OUT_HALF) {
                __half* C = (__half*)CoutV;
                *(__half2*)&C[(size_t)row * HID + col]       = __floats2half2_rn(s0, s1);
                *(__half2*)&C[(size_t)(row + 8) * HID + col] = __floats2half2_rn(s2, s3);
            } else {
                float* C = (float*)CoutV;
                *(float2*)&C[(size_t)row * HID + col]       = make_float2(s0, s1);
                *(float2*)&C[(size_t)(row + 8) * HID + col] = make_float2(s2, s3);
            }
        }
    }
}

// ---------------- launch ----------------
extern "C" void kernel_launch(void* const* d_in, const int* in_sizes, int n_in,
                              void* d_out, int out_size) {
    const float* atom_pos = (const float*)d_in[0];
    const float* dist_adj = (const float*)d_in[1];
    const float* atom_emb = (const float*)d_in[2];
    const float* W0 = (const float*)d_in[3];
    const float* b0 = (const float*)d_in[4];
    const float* W1 = (const float*)d_in[5];
    const float* b1 = (const float*)d_in[6];
    const float* W2 = (const float*)d_in[7];
    const float* b2 = (const float*)d_in[8];
    const float* W3 = (const float*)d_in[9];
    const float* b3 = (const float*)d_in[10];
    float* out = (float*)d_out;

    __half *bufA, *bufB, *wh;
    cudaGetSymbolAddress((void**)&bufA, g_hbufA);
    cudaGetSymbolAddress((void**)&bufB, g_hbufB);
    cudaGetSymbolAddress((void**)&wh,   g_wh);

    const __half* WH0 = wh;
    const __half* WH1 = wh + W0_ELEMS;
    const __half* WH2 = wh + W0_ELEMS + W_ELEMS;
    const __half* WH3 = wh + W0_ELEMS + 2 * W_ELEMS;

    build_kernel<<<NN / 8, 256>>>(dist_adj);
    concat_kernel<<<(NN * FIN + 255) / 256, 256>>>(atom_emb, atom_pos, bufA);
    wconv_kernel<<<(WH_TOTAL / 8 + 255) / 256, 256>>>(W0, W1, W2, W3);

    dim3 ggrid(HID / 128, NN / 128);   // (4, 64)

    // Layer 0: K = FIN = 128
    spmm_fp16<FIN><<<NN / 8, dim3(16, 8)>>>(bufA, bufB);
    gemm_f16_softplus<FIN, true><<<ggrid, 256>>>(bufB, WH0, b0, bufA);

    // Layer 1
    spmm_fp16<HID><<<NN / 2, dim3(64, 2)>>>(bufA, bufB);
    gemm_f16_softplus<HID, true><<<ggrid, 256>>>(bufB, WH1, b1, bufA);

    // Layer 2
    spmm_fp16<HID><<<NN / 2, dim3(64, 2)>>>(bufA, bufB);
    gemm_f16_softplus<HID, true><<<ggrid, 256>>>(bufB, WH2, b2, bufA);

    // Layer 3 -> fp32 to d_out
    spmm_fp16<HID><<<NN / 2, dim3(64, 2)>>>(bufA, bufB);
    gemm_f16_softplus<HID, false><<<ggrid, 256>>>(bufB, WH3, b3, out);
}

// round 15
// speedup vs baseline: 1.0034x; 1.0015x over previous
#include <cuda_runtime.h>
#include <cuda_fp16.h>
#include <math.h>
#include <stdint.h>

// Problem constants (fixed by reference)
#define NN   8192
#define EMB  125
#define POSD 3
#define FIN  128     // EMB + POSD
#define HID  512
#define SLOTS 256

#define W0_ELEMS (FIN * HID)          // 65536
#define W_ELEMS  (HID * HID)          // 262144
#define WH_TOTAL (W0_ELEMS + 3 * W_ELEMS)  // 851968

// ---------------- device scratch (no allocation allowed) ----------------
__device__ int   g_col[NN * SLOTS];
__device__ int   g_deg[NN];
__device__ float g_norm[NN];
__device__ __align__(16) __half g_hbufA[NN * HID];   // 8 MB
__device__ __align__(16) __half g_hbufB[NN * HID];   // 8 MB
__device__ __align__(16) __half g_wh[WH_TOTAL];      // 1.7 MB fp16 weights

// ---------------- 1) build sparse structure + norms ----------------
__global__ void build_kernel(const float* __restrict__ adj) {
    int warp = threadIdx.x >> 5;
    int lane = threadIdx.x & 31;
    int row  = blockIdx.x * (blockDim.x >> 5) + warp;
    if (row >= NN) return;

    const float* arow = adj + (size_t)row * NN;
    int cnt = 0;
    for (int c0 = 0; c0 < NN; c0 += 32) {
        int c = c0 + lane;
        float v = arow[c];
        bool pred = (v != 0.0f) && (c != row);
        unsigned mask = __ballot_sync(0xFFFFFFFFu, pred);
        int pos = cnt + __popc(mask & ((1u << lane) - 1u));
        if (pred && pos < SLOTS) g_col[row * SLOTS + pos] = c;
        cnt += __popc(mask);
    }
    if (lane == 0) {
        g_deg[row]  = (cnt < SLOTS) ? cnt : SLOTS;
        g_norm[row] = rsqrtf(fmaxf((float)cnt, 1.0f));
    }
}

// ---------------- 2) concat emb||pos -> fp16 feat [NN, FIN] ----------------
__global__ void concat_kernel(const float* __restrict__ emb,
                              const float* __restrict__ pos,
                              __half* __restrict__ out) {
    int idx = blockIdx.x * blockDim.x + threadIdx.x;
    if (idx >= NN * FIN) return;
    int i = idx / FIN, c = idx % FIN;
    float v = (c < EMB) ? emb[i * EMB + c] : pos[i * POSD + (c - EMB)];
    out[idx] = __float2half(v);
}

// ---------------- 2b) convert weights to fp16 (compact layout) ----------------
__global__ void wconv_kernel(const float* __restrict__ W0, const float* __restrict__ W1,
                             const float* __restrict__ W2, const float* __restrict__ W3) {
    int idx = (blockIdx.x * blockDim.x + threadIdx.x) * 8;
    if (idx >= WH_TOTAL) return;
    const float* src;
    if (idx < W0_ELEMS)                    src = W0 + idx;
    else if (idx < W0_ELEMS + W_ELEMS)     src = W1 + (idx - W0_ELEMS);
    else if (idx < W0_ELEMS + 2 * W_ELEMS) src = W2 + (idx - W0_ELEMS - W_ELEMS);
    else                                   src = W3 + (idx - W0_ELEMS - 2 * W_ELEMS);
    float4 a = *(const float4*)src;
    float4 b = *(const float4*)(src + 4);
    __half2 h[4];
    h[0] = __floats2half2_rn(a.x, a.y);
    h[1] = __floats2half2_rn(a.z, a.w);
    h[2] = __floats2half2_rn(b.x, b.y);
    h[3] = __floats2half2_rn(b.z, b.w);
    *(uint4*)&g_wh[idx] = *(uint4*)h;
}

// ---------------- 3) SpMM fp16: agg[i,:] = norm_i * sum_j norm_j * feat[j,:] ----------------
// blockDim = (C/8, 128/(C/8)); each thread handles 8 halves (one uint4).
template <int C>
__global__ void spmm_fp16(const __half* __restrict__ feat, __half* __restrict__ agg) {
    constexpr int TX = C / 8;
    constexpr int TY = 128 / TX;
    int y = threadIdx.y;
    int i = blockIdx.x * TY + y;
    __shared__ int   sc[TY][SLOTS];
    __shared__ float sw[TY][SLOTS];
    int d = g_deg[i];
    for (int k = threadIdx.x; k < d; k += TX) {
        int j = g_col[i * SLOTS + k];
        sc[y][k] = j;
        sw[y][k] = g_norm[j];
    }
    __syncthreads();
    int c8 = threadIdx.x * 8;
    float acc[8] = {0.f, 0.f, 0.f, 0.f, 0.f, 0.f, 0.f, 0.f};
    for (int k = 0; k < d; k++) {
        float w = sw[y][k];
        uint4 v = *(const uint4*)&feat[(size_t)sc[y][k] * C + c8];
        const __half2* hv = (const __half2*)&v;
#pragma unroll
        for (int q = 0; q < 4; q++) {
            float2 f = __half22float2(hv[q]);
            acc[q * 2 + 0] = fmaf(w, f.x, acc[q * 2 + 0]);
            acc[q * 2 + 1] = fmaf(w, f.y, acc[q * 2 + 1]);
        }
    }
    float ni = g_norm[i];
    __half2 ho[4];
#pragma unroll
    for (int q = 0; q < 4; q++)
        ho[q] = __floats2half2_rn(acc[q * 2] * ni, acc[q * 2 + 1] * ni);
    *(uint4*)&agg[(size_t)i * C + c8] = *(uint4*)ho;
}

// ---------------- 4) fp16 tensor GEMM + bias + softplus ----------------
__device__ __forceinline__ void mma_f16(float* d, const uint32_t* a, const uint32_t* b) {
    asm volatile(
        "mma.sync.aligned.m16n8k16.row.col.f32.f16.f16.f32 "
        "{%0,%1,%2,%3}, {%4,%5,%6,%7}, {%8,%9}, {%0,%1,%2,%3};\n"
        : "+f"(d[0]), "+f"(d[1]), "+f"(d[2]), "+f"(d[3])
        : "r"(a[0]), "r"(a[1]), "r"(a[2]), "r"(a[3]), "r"(b[0]), "r"(b[1]));
}

__device__ __forceinline__ void ldmat_x4(uint32_t* r, uint32_t saddr) {
    asm volatile(
        "ldmatrix.sync.aligned.m8n8.x4.shared.b16 {%0,%1,%2,%3}, [%4];\n"
        : "=r"(r[0]), "=r"(r[1]), "=r"(r[2]), "=r"(r[3])
        : "r"(saddr));
}

__device__ __forceinline__ void ldmat_x4_trans(uint32_t* r, uint32_t saddr) {
    asm volatile(
        "ldmatrix.sync.aligned.m8n8.x4.trans.shared.b16 {%0,%1,%2,%3}, [%4];\n"
        : "=r"(r[0]), "=r"(r[1]), "=r"(r[2]), "=r"(r[3])
        : "r"(saddr));
}

// Block tile 128x128, BK=32 (fp16), 8 warps (2x4), warp tile 64x32.
// A smem [m][k] LDA=40 halves; B smem [k][n] LDB=136 halves. All ldmatrix paths
// and STS.128 store phases verified bank-conflict-free.
template <int K, bool OUT_HALF>
__global__ __launch_bounds__(256, 2) void gemm_f16_softplus(
    const __half* __restrict__ A,
    const __half* __restrict__ Bh,
    const float* __restrict__ bias,
    void* __restrict__ CoutV)
{
    constexpr int BM = 128, BN = 128, BK = 32;
    constexpr int LDA = BK + 8;   // 40 halves (80B; rows 0..7 -> distinct bank quads)
    constexpr int LDB = BN + 8;   // 136 halves (272B; k-rows stride 4 banks)

    __shared__ __align__(16) __half As[2][BM][LDA];  // 20 KB
    __shared__ __align__(16) __half Bs[2][BK][LDB];  // 17 KB

    int tid  = threadIdx.x;
    int lane = tid & 31;
    int warp = tid >> 5;
    int g    = lane >> 2;
    int tg   = lane & 3;
    int wm   = (warp & 1) * 64;
    int wn   = (warp >> 1) * 32;
    int m0   = blockIdx.y * BM;
    int n0   = blockIdx.x * BN;

    int lmrow = lane & 15;
    int lmhi  = (lane >> 4) * 8;

    float acc[4][4][4];
#pragma unroll
    for (int i = 0; i < 4; i++)
#pragma unroll
        for (int j = 0; j < 4; j++)
#pragma unroll
            for (int r = 0; r < 4; r++) acc[i][j][r] = 0.0f;

    // global staging regs
    uint4 pa[2], pb[2];
    // A mapping: i in {0,1}: row = tid&127, col8 = ((tid>>7)*2 + i)*8
    int a_row = tid & 127;
    int a_c0  = ((tid >> 7) * 2) * 8;
    // B mapping: f = i*256 + tid: row = f>>4, col8 = (f&15)*8

    auto loadg = [&](int k0) {
#pragma unroll
        for (int i = 0; i < 2; i++) {
            pa[i] = *(const uint4*)&A[(size_t)(m0 + a_row) * K + k0 + a_c0 + i * 8];
            int f  = i * 256 + tid;
            int rb = f >> 4, cb = (f & 15) * 8;
            pb[i] = *(const uint4*)&Bh[(size_t)(k0 + rb) * HID + n0 + cb];
        }
    };
    auto stores = [&](int buf) {
#pragma unroll
        for (int i = 0; i < 2; i++) {
            *(uint4*)&As[buf][a_row][a_c0 + i * 8] = pa[i];
            int f  = i * 256 + tid;
            int rb = f >> 4, cb = (f & 15) * 8;
            *(uint4*)&Bs[buf][rb][cb] = pb[i];
        }
    };
    auto compute = [&](int buf) {
#pragma unroll
        for (int ks = 0; ks < BK; ks += 16) {
            uint32_t a[4][4], b[4][2];
#pragma unroll
            for (int i = 0; i < 4; i++) {
                uint32_t saddr = (uint32_t)__cvta_generic_to_shared(
                    &As[buf][wm + i * 16 + lmrow][ks + lmhi]);
                ldmat_x4(a[i], saddr);
            }
#pragma unroll
            for (int jj = 0; jj < 2; jj++) {
                uint32_t r[4];
                uint32_t saddr = (uint32_t)__cvta_generic_to_shared(
                    &Bs[buf][ks + lmrow][wn + jj * 16 + lmhi]);
                ldmat_x4_trans(r, saddr);
                b[jj * 2 + 0][0] = r[0]; b[jj * 2 + 0][1] = r[1];
                b[jj * 2 + 1][0] = r[2]; b[jj * 2 + 1][1] = r[3];
            }
#pragma unroll
            for (int i = 0; i < 4; i++)
#pragma unroll
                for (int j = 0; j < 4; j++)
                    mma_f16(acc[i][j], a[i], b[j]);
        }
    };

    constexpr int NK = K / BK;
    loadg(0);
    stores(0);
    __syncthreads();
#pragma unroll 1
    for (int t = 0; t < NK; t++) {
        if (t + 1 < NK) loadg((t + 1) * BK);
        compute(t & 1);
        if (t + 1 < NK) {
            stores((t + 1) & 1);
            __syncthreads();
        }
    }

    // epilogue: bias + fast stable softplus
#pragma unroll
    for (int i = 0; i < 4; i++) {
        int row = m0 + wm + i * 16 + g;
#pragma unroll
        for (int j = 0; j < 4; j++) {
            int col = n0 + wn + j * 8 + tg * 2;
            float bx = bias[col], by = bias[col + 1];
            float x0 = acc[i][j][0] + bx;
            float x1 = acc[i][j][1] + by;
            float x2 = acc[i][j][2] + bx;
            float x3 = acc[i][j][3] + by;
            float s0 = fmaxf(x0, 0.f) + __logf(1.0f + __expf(-fabsf(x0)));
            float s1 = fmaxf(x1, 0.f) + __logf(1.0f + __expf(-fabsf(x1)));
            float s2 = fmaxf(x2, 0.f) + __logf(1.0f + __expf(-fabsf(x2)));
            float s3 = fmaxf(x3, 0.f) + __logf(1.0f + __expf(-fabsf(x3)));
            if (OUT_HALF) {
                __half* C = (__half*)CoutV;
                *(__half2*)&C[(size_t)row * HID + col]       = __floats2half2_rn(s0, s1);
                *(__half2*)&C[(size_t)(row + 8) * HID + col] = __floats2half2_rn(s2, s3);
            } else {
                float* C = (float*)CoutV;
                *(float2*)&C[(size_t)row * HID + col]       = make_float2(s0, s1);
                *(float2*)&C[(size_t)(row + 8) * HID + col] = make_float2(s2, s3);
            }
        }
    }
}

// ---------------- launch ----------------
extern "C" void kernel_launch(void* const* d_in, const int* in_sizes, int n_in,
                              void* d_out, int out_size) {
    const float* atom_pos = (const float*)d_in[0];
    const float* dist_adj = (const float*)d_in[1];
    const float* atom_emb = (const float*)d_in[2];
    const float* W0 = (const float*)d_in[3];
    const float* b0 = (const float*)d_in[4];
    const float* W1 = (const float*)d_in[5];
    const float* b1 = (const float*)d_in[6];
    const float* W2 = (const float*)d_in[7];
    const float* b2 = (const float*)d_in[8];
    const float* W3 = (const float*)d_in[9];
    const float* b3 = (const float*)d_in[10];
    float* out = (float*)d_out;

    __half *bufA, *bufB, *wh;
    cudaGetSymbolAddress((void**)&bufA, g_hbufA);
    cudaGetSymbolAddress((void**)&bufB, g_hbufB);
    cudaGetSymbolAddress((void**)&wh,   g_wh);

    const __half* WH0 = wh;
    const __half* WH1 = wh + W0_ELEMS;
    const __half* WH2 = wh + W0_ELEMS + W_ELEMS;
    const __half* WH3 = wh + W0_ELEMS + 2 * W_ELEMS;

    build_kernel<<<NN / 8, 256>>>(dist_adj);
    concat_kernel<<<(NN * FIN + 255) / 256, 256>>>(atom_emb, atom_pos, bufA);
    wconv_kernel<<<(WH_TOTAL / 8 + 255) / 256, 256>>>(W0, W1, W2, W3);

    dim3 ggrid(HID / 128, NN / 128);   // (4, 64)

    // Layer 0: K = FIN = 128
    spmm_fp16<FIN><<<NN / 8, dim3(16, 8)>>>(bufA, bufB);
    gemm_f16_softplus<FIN, true><<<ggrid, 256>>>(bufB, WH0, b0, bufA);

    // Layer 1
    spmm_fp16<HID><<<NN / 2, dim3(64, 2)>>>(bufA, bufB);
    gemm_f16_softplus<HID, true><<<ggrid, 256>>>(bufB, WH1, b1, bufA);

    // Layer 2
    spmm_fp16<HID><<<NN / 2, dim3(64, 2)>>>(bufA, bufB);
    gemm_f16_softplus<HID, true><<<ggrid, 256>>>(bufB, WH2, b2, bufA);

    // Layer 3 -> fp32 to d_out
    spmm_fp16<HID><<<NN / 2, dim3(64, 2)>>>(bufA, bufB);
    gemm_f16_softplus<HID, false><<<ggrid, 256>>>(bufB, WH3, b3, out);
}